// round 4
// baseline (speedup 1.0000x reference)
#include <cuda_runtime.h>

// PercolationQ: per-patch occupancy fraction -> threshold -> mean over patches.
// Pure HBM-bound streaming reduction over three 50 MB fp32 tensors.
//
// Layout:
//   x4 : [3, 64, 4096, 4, 4]   row (c,b) = 65536 contiguous floats, patch = 16 floats
//   x8 : [3, 64, 1024, 8, 8]   row = 65536 floats, patch = 64 floats
//   x16: [3, 64,  256,16,16]   row = 65536 floats, patch = 256 floats
// Output: [q4(3,64), q8(3,64), q16(3,64)] concatenated = 576 floats.
//
// Single fused kernel: 2304 blocks x 256 threads, every block streams exactly
// 64 KB (streaming __ldcs loads). Deterministic per-block partial counts ->
// __device__ scratch, then the LAST block (threadfence-reduction ticket
// pattern) performs the finalize in-kernel — no second graph node.

#define PERC_THR 0.59275f

// 192 rows * 4 blocks-per-row for each tensor
__device__ int g_part4[768];
__device__ int g_part8[768];
__device__ int g_part16[768];
__device__ unsigned int g_ticket = 0;   // self-resetting -> deterministic replays

__device__ __forceinline__ float red4(float4 a) {
    return (a.x + a.y) + (a.z + a.w);
}

// Returns valid total only on threadIdx.x == 0.
__device__ __forceinline__ int block_reduce_count(int c, int* sh) {
    c = __reduce_add_sync(0xffffffffu, c);
    int warp = threadIdx.x >> 5;
    if ((threadIdx.x & 31) == 0) sh[warp] = c;
    __syncthreads();
    if (threadIdx.x == 0) {
        int s = 0;
#pragma unroll
        for (int i = 0; i < 8; i++) s += sh[i];
        return s;
    }
    return 0;
}

__global__ void __launch_bounds__(256)
perc_kernel(const float* __restrict__ x4,
            const float* __restrict__ x8,
            const float* __restrict__ x16,
            float* __restrict__ out) {
    __shared__ int sh[8];
    __shared__ bool sh_last;
    const int bid = blockIdx.x;
    const int tid = threadIdx.x;

    if (bid < 768) {
        // ---- x4: row = bid/4, 1024 patches per block, 4 patches per thread ----
        const int row = bid >> 2;
        const int blk = bid & 3;
        const float4* base =
            (const float4*)(x4 + (size_t)row * 65536) + (size_t)blk * 1024 * 4;
        int cnt = 0;
#pragma unroll
        for (int k = 0; k < 4; k++) {
            const float4* p = base + (size_t)(k * 256 + tid) * 4;
            float4 a0 = __ldcs(p + 0);
            float4 a1 = __ldcs(p + 1);
            float4 a2 = __ldcs(p + 2);
            float4 a3 = __ldcs(p + 3);
            float s = (red4(a0) + red4(a1)) + (red4(a2) + red4(a3));
            cnt += (s * 0.0625f >= PERC_THR) ? 1 : 0;
        }
        int total = block_reduce_count(cnt, sh);
        if (tid == 0) g_part4[bid] = total;
    } else if (bid < 1536) {
        // ---- x8: 256 patches per block, 1 patch per thread (16 float4) ----
        const int b = bid - 768;
        const int row = b >> 2;
        const int blk = b & 3;
        const float4* p = (const float4*)(x8 + (size_t)row * 65536) +
                          ((size_t)blk * 256 + tid) * 16;
        // 4 independent accumulators to keep all 16 loads in flight
        float4 acc0 = make_float4(0.f, 0.f, 0.f, 0.f);
        float4 acc1 = make_float4(0.f, 0.f, 0.f, 0.f);
        float4 acc2 = make_float4(0.f, 0.f, 0.f, 0.f);
        float4 acc3 = make_float4(0.f, 0.f, 0.f, 0.f);
#pragma unroll
        for (int i = 0; i < 4; i++) {
            float4 v0 = __ldcs(p + i * 4 + 0);
            float4 v1 = __ldcs(p + i * 4 + 1);
            float4 v2 = __ldcs(p + i * 4 + 2);
            float4 v3 = __ldcs(p + i * 4 + 3);
            acc0.x += v0.x; acc0.y += v0.y; acc0.z += v0.z; acc0.w += v0.w;
            acc1.x += v1.x; acc1.y += v1.y; acc1.z += v1.z; acc1.w += v1.w;
            acc2.x += v2.x; acc2.y += v2.y; acc2.z += v2.z; acc2.w += v2.w;
            acc3.x += v3.x; acc3.y += v3.y; acc3.z += v3.z; acc3.w += v3.w;
        }
        float s = (red4(acc0) + red4(acc1)) + (red4(acc2) + red4(acc3));
        int cnt = (s * 0.015625f >= PERC_THR) ? 1 : 0;
        int total = block_reduce_count(cnt, sh);
        if (tid == 0) g_part8[b] = total;
    } else {
        // ---- x16: 64 patches per block, 4 threads per patch (16 float4 each) ----
        const int b = bid - 1536;
        const int row = b >> 2;
        const int blk = b & 3;
        const int patch = blk * 64 + (tid >> 2);
        const int sub = tid & 3;
        const float4* p = (const float4*)(x16 + (size_t)row * 65536) +
                          (size_t)patch * 64 + (size_t)sub * 16;
        float4 acc0 = make_float4(0.f, 0.f, 0.f, 0.f);
        float4 acc1 = make_float4(0.f, 0.f, 0.f, 0.f);
        float4 acc2 = make_float4(0.f, 0.f, 0.f, 0.f);
        float4 acc3 = make_float4(0.f, 0.f, 0.f, 0.f);
#pragma unroll
        for (int i = 0; i < 4; i++) {
            float4 v0 = __ldcs(p + i * 4 + 0);
            float4 v1 = __ldcs(p + i * 4 + 1);
            float4 v2 = __ldcs(p + i * 4 + 2);
            float4 v3 = __ldcs(p + i * 4 + 3);
            acc0.x += v0.x; acc0.y += v0.y; acc0.z += v0.z; acc0.w += v0.w;
            acc1.x += v1.x; acc1.y += v1.y; acc1.z += v1.z; acc1.w += v1.w;
            acc2.x += v2.x; acc2.y += v2.y; acc2.z += v2.z; acc2.w += v2.w;
            acc3.x += v3.x; acc3.y += v3.y; acc3.z += v3.z; acc3.w += v3.w;
        }
        float s = (red4(acc0) + red4(acc1)) + (red4(acc2) + red4(acc3));
        // combine the 4 sub-sums of this patch (lanes 4g..4g+3)
        s += __shfl_xor_sync(0xffffffffu, s, 1);
        s += __shfl_xor_sync(0xffffffffu, s, 2);
        int cnt = (sub == 0 && (s * 0.00390625f >= PERC_THR)) ? 1 : 0;
        int total = block_reduce_count(cnt, sh);
        if (tid == 0) g_part16[b] = total;
    }

    // ---- last-block finalize (threadfence-reduction pattern) ----
    if (tid == 0) {
        __threadfence();                       // publish g_part writes
        unsigned int t = atomicAdd(&g_ticket, 1);
        sh_last = (t == gridDim.x - 1);
    }
    __syncthreads();
    if (sh_last) {
        // 576 outputs, 256 threads -> up to 3 per thread
        for (int t = tid; t < 576; t += 256) {
            const int tensor = t / 192;        // 0: x4, 1: x8, 2: x16
            const int row = t % 192;
            const int* part = (tensor == 0) ? g_part4
                            : (tensor == 1) ? g_part8 : g_part16;
            int c = part[row * 4 + 0] + part[row * 4 + 1] +
                    part[row * 4 + 2] + part[row * 4 + 3];
            const float invP = (tensor == 0) ? (1.0f / 4096.0f)
                             : (tensor == 1) ? (1.0f / 1024.0f)
                                             : (1.0f / 256.0f);
            out[t] = (float)c * invP;
        }
        if (tid == 0) g_ticket = 0;            // reset for next graph replay
    }
}

extern "C" void kernel_launch(void* const* d_in, const int* in_sizes, int n_in,
                              void* d_out, int out_size) {
    const float* x4  = (const float*)d_in[0];
    const float* x8  = (const float*)d_in[1];
    const float* x16 = (const float*)d_in[2];
    float* out = (float*)d_out;

    perc_kernel<<<2304, 256>>>(x4, x8, x16, out);
}

// round 5
// speedup vs baseline: 2.1316x; 2.1316x over previous
#include <cuda_runtime.h>

// PercolationQ: per-patch occupancy fraction -> threshold -> mean over patches.
// Pure HBM-bound streaming reduction over three 50 MB fp32 tensors.
//
// Layout (flat view):
//   x4 : [3,64,4096,4,4]   row (c,b) = 65536 floats, patch = 16 floats
//   x8 : [3,64,1024,8,8]   row = 65536 floats, patch = 64 floats
//   x16: [3,64, 256,16,16] row = 65536 floats, patch = 256 floats
// Output: [q4(3,64), q8(3,64), q16(3,64)] = 576 floats.
//
// R4: fully COALESCED warp loads. Each warp owns a contiguous 8 KB segment;
// iteration i, lane l loads float4 seg[i*32 + l] -> one LDG.128 touches only
// 4 cache lines (minimum wavefronts). Patch sums assembled across lanes with
// shfl_xor segmented reductions. Last-block in-kernel finalize (no 2nd node).

#define PERC_THR 0.59275f

// 192 rows * 4 blocks-per-row for each tensor
__device__ int g_part4[768];
__device__ int g_part8[768];
__device__ int g_part16[768];
__device__ unsigned int g_ticket = 0;   // self-resetting -> deterministic replays

__device__ __forceinline__ float red4(float4 a) {
    return (a.x + a.y) + (a.z + a.w);
}

// Returns valid total only on threadIdx.x == 0.
__device__ __forceinline__ int block_reduce_count(int c, int* sh) {
    c = __reduce_add_sync(0xffffffffu, c);
    int warp = threadIdx.x >> 5;
    if ((threadIdx.x & 31) == 0) sh[warp] = c;
    __syncthreads();
    if (threadIdx.x == 0) {
        int s = 0;
#pragma unroll
        for (int i = 0; i < 8; i++) s += sh[i];
        return s;
    }
    return 0;
}

__global__ void __launch_bounds__(256)
perc_kernel(const float* __restrict__ x4,
            const float* __restrict__ x8,
            const float* __restrict__ x16,
            float* __restrict__ out) {
    __shared__ int sh[8];
    __shared__ bool sh_last;
    const int bid  = blockIdx.x;
    const int tid  = threadIdx.x;
    const int warp = tid >> 5;
    const int lane = tid & 31;

    int cnt = 0;

    if (bid < 768) {
        // ---- x4: block = 64 KB flat chunk; warp = 8 KB = 2048 floats = 128 patches
        // Each iteration: warp loads 512 contiguous bytes = 128 floats = 8 patches.
        // Patch = lanes 4k..4k+3 (one float4 each).
        const float4* seg = (const float4*)x4 + (size_t)bid * 4096 + warp * 512;
#pragma unroll
        for (int i = 0; i < 16; i++) {
            float4 v = seg[i * 32 + lane];
            float s = red4(v);
            s += __shfl_xor_sync(0xffffffffu, s, 1);
            s += __shfl_xor_sync(0xffffffffu, s, 2);
            cnt += ((lane & 3) == 0 && (s * 0.0625f >= PERC_THR)) ? 1 : 0;
        }
        int total = block_reduce_count(cnt, sh);
        if (tid == 0) g_part4[bid] = total;
    } else if (bid < 1536) {
        // ---- x8: warp iteration covers 128 floats = 2 patches (lanes 0-15 / 16-31)
        const int b = bid - 768;
        const float4* seg = (const float4*)x8 + (size_t)b * 4096 + warp * 512;
#pragma unroll
        for (int i = 0; i < 16; i++) {
            float4 v = seg[i * 32 + lane];
            float s = red4(v);
            s += __shfl_xor_sync(0xffffffffu, s, 1);
            s += __shfl_xor_sync(0xffffffffu, s, 2);
            s += __shfl_xor_sync(0xffffffffu, s, 4);
            s += __shfl_xor_sync(0xffffffffu, s, 8);
            cnt += ((lane & 15) == 0 && (s * 0.015625f >= PERC_THR)) ? 1 : 0;
        }
        int total = block_reduce_count(cnt, sh);
        if (tid == 0) g_part8[b] = total;
    } else {
        // ---- x16: patch = 256 floats = 2 warp iterations -> pair then full reduce
        const int b = bid - 1536;
        const float4* seg = (const float4*)x16 + (size_t)b * 4096 + warp * 512;
#pragma unroll
        for (int i = 0; i < 16; i += 2) {
            float4 v0 = seg[i * 32 + lane];
            float4 v1 = seg[(i + 1) * 32 + lane];
            float s = red4(v0) + red4(v1);
            s += __shfl_xor_sync(0xffffffffu, s, 1);
            s += __shfl_xor_sync(0xffffffffu, s, 2);
            s += __shfl_xor_sync(0xffffffffu, s, 4);
            s += __shfl_xor_sync(0xffffffffu, s, 8);
            s += __shfl_xor_sync(0xffffffffu, s, 16);
            cnt += (lane == 0 && (s * 0.00390625f >= PERC_THR)) ? 1 : 0;
        }
        int total = block_reduce_count(cnt, sh);
        if (tid == 0) g_part16[b] = total;
    }

    // ---- last-block finalize (threadfence-reduction pattern) ----
    if (tid == 0) {
        __threadfence();                       // publish g_part writes
        unsigned int t = atomicAdd(&g_ticket, 1);
        sh_last = (t == gridDim.x - 1);
    }
    __syncthreads();
    if (sh_last) {
        for (int t = tid; t < 576; t += 256) {
            const int tensor = t / 192;        // 0: x4, 1: x8, 2: x16
            const int row = t % 192;
            const int* part = (tensor == 0) ? g_part4
                            : (tensor == 1) ? g_part8 : g_part16;
            int c = part[row * 4 + 0] + part[row * 4 + 1] +
                    part[row * 4 + 2] + part[row * 4 + 3];
            const float invP = (tensor == 0) ? (1.0f / 4096.0f)
                             : (tensor == 1) ? (1.0f / 1024.0f)
                                             : (1.0f / 256.0f);
            out[t] = (float)c * invP;
        }
        if (tid == 0) g_ticket = 0;            // reset for next graph replay
    }
}

extern "C" void kernel_launch(void* const* d_in, const int* in_sizes, int n_in,
                              void* d_out, int out_size) {
    const float* x4  = (const float*)d_in[0];
    const float* x8  = (const float*)d_in[1];
    const float* x16 = (const float*)d_in[2];
    float* out = (float*)d_out;

    perc_kernel<<<2304, 256>>>(x4, x8, x16, out);
}

// round 6
// speedup vs baseline: 2.1339x; 1.0011x over previous
#include <cuda_runtime.h>

// PercolationQ: per-patch occupancy fraction -> threshold -> mean over patches.
// Pure HBM-bound streaming reduction over three 50 MB fp32 tensors.
//
// Layout (flat view):
//   x4 : [3,64,4096,4,4]   patch = 16 floats  = 4  float4
//   x8 : [3,64,1024,8,8]   patch = 64 floats  = 16 float4
//   x16: [3,64, 256,16,16] patch = 256 floats = 64 float4
// Output: [q4(3,64), q8(3,64), q16(3,64)] = 576 floats.
//
// R5: two-phase per block. Phase 1 streams 64 KB fully coalesced (warp-LDG.128
// = 512 contiguous bytes) and writes one scalar partial per float4 to swizzled
// smem -- NO cross-lane dependency in the load loop. Phase 2 reduces partials
// from smem (identical gather pattern for all three tensors). Last block does
// the finalize in-kernel (ticket pattern) -- single graph node.

#define PERC_THR 0.59275f

__device__ int g_part[2304];            // per-block patch counts
__device__ unsigned int g_ticket = 0;   // self-resetting -> deterministic replays

__device__ __forceinline__ float red4(float4 a) {
    return (a.x + a.y) + (a.z + a.w);
}

__device__ __forceinline__ int swz(int g) {   // group swizzle (conflict-free)
    return g ^ ((g >> 3) & 7);
}

// Returns valid total only on threadIdx.x == 0.
__device__ __forceinline__ int block_reduce_count(int c, int* sh) {
    c = __reduce_add_sync(0xffffffffu, c);
    int warp = threadIdx.x >> 5;
    if ((threadIdx.x & 31) == 0) sh[warp] = c;
    __syncthreads();
    if (threadIdx.x == 0) {
        int s = 0;
#pragma unroll
        for (int i = 0; i < 8; i++) s += sh[i];
        return s;
    }
    return 0;
}

__global__ void __launch_bounds__(256)
perc_kernel(const float* __restrict__ x4,
            const float* __restrict__ x8,
            const float* __restrict__ x16,
            float* __restrict__ out) {
    __shared__ float s_part[4096];      // 16 KB: one partial per float4, swizzled
    __shared__ int sh[8];
    __shared__ bool sh_last;

    const int bid  = blockIdx.x;
    const int tid  = threadIdx.x;
    const int warp = tid >> 5;
    const int lane = tid & 31;

    // Which tensor does this block stream? (768 x 64KB chunks each)
    const float* src;
    int chunk;
    if (bid < 768)       { src = x4;  chunk = bid; }
    else if (bid < 1536) { src = x8;  chunk = bid - 768; }
    else                 { src = x16; chunk = bid - 1536; }

    // ---- Phase 1: coalesced stream, per-float4 partials -> swizzled smem ----
    // f4 index j = warp*512 + i*32 + lane; scalar-group G = j>>2, comp = lane&3.
    const float4* seg = (const float4*)src + (size_t)chunk * 4096 + warp * 512;
    const int gwarp = warp * 128;
    const int gsub  = lane >> 2;
    const int comp  = lane & 3;
#pragma unroll
    for (int io = 0; io < 16; io += 4) {
        float4 v0 = seg[(io + 0) * 32 + lane];
        float4 v1 = seg[(io + 1) * 32 + lane];
        float4 v2 = seg[(io + 2) * 32 + lane];
        float4 v3 = seg[(io + 3) * 32 + lane];
        s_part[4 * swz(gwarp + (io + 0) * 8 + gsub) + comp] = red4(v0);
        s_part[4 * swz(gwarp + (io + 1) * 8 + gsub) + comp] = red4(v1);
        s_part[4 * swz(gwarp + (io + 2) * 8 + gsub) + comp] = red4(v2);
        s_part[4 * swz(gwarp + (io + 3) * 8 + gsub) + comp] = red4(v3);
    }
    __syncthreads();

    // ---- Phase 2: gather 4 float4-of-partials per thread (groups 4t..4t+3) ----
    const float4* sp4 = (const float4*)s_part;
    float4 p0 = sp4[swz(4 * tid + 0)];
    float4 p1 = sp4[swz(4 * tid + 1)];
    float4 p2 = sp4[swz(4 * tid + 2)];
    float4 p3 = sp4[swz(4 * tid + 3)];

    int cnt = 0;
    if (bid < 768) {
        // x4: each float4-of-partials is one whole patch (4 patches/thread)
        cnt += (red4(p0) * 0.0625f >= PERC_THR) ? 1 : 0;
        cnt += (red4(p1) * 0.0625f >= PERC_THR) ? 1 : 0;
        cnt += (red4(p2) * 0.0625f >= PERC_THR) ? 1 : 0;
        cnt += (red4(p3) * 0.0625f >= PERC_THR) ? 1 : 0;
    } else if (bid < 1536) {
        // x8: all 16 partials form one patch
        float s = (red4(p0) + red4(p1)) + (red4(p2) + red4(p3));
        cnt = (s * 0.015625f >= PERC_THR) ? 1 : 0;
    } else {
        // x16: 4 threads per patch (threads 4q..4q+3), combine with 2 shfls
        float s = (red4(p0) + red4(p1)) + (red4(p2) + red4(p3));
        s += __shfl_xor_sync(0xffffffffu, s, 1);
        s += __shfl_xor_sync(0xffffffffu, s, 2);
        cnt = ((tid & 3) == 0 && (s * 0.00390625f >= PERC_THR)) ? 1 : 0;
    }

    int total = block_reduce_count(cnt, sh);
    if (tid == 0) g_part[bid] = total;

    // ---- last-block finalize (threadfence-reduction pattern) ----
    if (tid == 0) {
        __threadfence();                       // publish g_part writes
        unsigned int t = atomicAdd(&g_ticket, 1);
        sh_last = (t == gridDim.x - 1);
    }
    __syncthreads();
    if (sh_last) {
        for (int t = tid; t < 576; t += 256) {
            const int tensor = t / 192;        // 0: x4, 1: x8, 2: x16
            const int row = t % 192;
            const int* part = g_part + tensor * 768 + row * 4;
            int c = part[0] + part[1] + part[2] + part[3];
            const float invP = (tensor == 0) ? (1.0f / 4096.0f)
                             : (tensor == 1) ? (1.0f / 1024.0f)
                                             : (1.0f / 256.0f);
            out[t] = (float)c * invP;
        }
        if (tid == 0) g_ticket = 0;            // reset for next graph replay
    }
}

extern "C" void kernel_launch(void* const* d_in, const int* in_sizes, int n_in,
                              void* d_out, int out_size) {
    const float* x4  = (const float*)d_in[0];
    const float* x8  = (const float*)d_in[1];
    const float* x16 = (const float*)d_in[2];
    float* out = (float*)d_out;

    perc_kernel<<<2304, 256>>>(x4, x8, x16, out);
}